// round 16
// baseline (speedup 1.0000x reference)
#include <cuda_runtime.h>
#include <cuda_fp16.h>
#include <stdint.h>

// ContextAwareTracker: LSTM enc(50)+dec(12), B=16384, H=128, I=5.
// Round 16: overlap fix. R15 was co-bound (tensor 52.5%, L1 52.0%) with wall
// ~1.9x per-pipe busy -> serial phases (A-frag LDSM, MMA bursts, MUFU/shuffle
// epilogue) inside one CTA. Split to 256 CTAs x 256 thr, 2 CTAs/SM (95KB smem
// each): independent CTAs interleave phases and fill each other's bubbles.
// Per-row math bit-identical to R15 (fp16 single-A + W hi/lo, 2 MMA sweeps).
// NOTE: tcgen05 unavailable (harness PTX target sm_103 base) - mma.sync only.

#define BDIM 256
#define ROWS 64           // batch rows per CTA
#define ROWB 304          // conflict-free ldmatrix stride; K pad 152
#define ABUF 19456        // 64 * 304, single fp16 A buffer
#define SM_B ABUF
#define WSPLIT 19456      // 64 * 304
#define WBLK  38912       // 64 cols x 2 splits x 304B
#define SMEM_TOTAL (ABUF + 2 * WBLK)   // 97280 -> 2 CTAs/SM
#define NBLOCKS 496       // 62 steps * 8 blocks

__device__ __half g_wpack[16 * 19456];  // [net 2][chunk64 8][split 2][n 64][k 152]

// gate col interleave: C = 4*unit + gate (0=i,1=f,2=g,3=o)
__global__ void prep_kernel(const float* __restrict__ eWih, const float* __restrict__ eWhh,
                            const float* __restrict__ ebih, const float* __restrict__ ebhh,
                            const float* __restrict__ dWih, const float* __restrict__ dWhh,
                            const float* __restrict__ dbih, const float* __restrict__ dbhh)
{
    int idx = blockIdx.x * blockDim.x + threadIdx.x;
    if (idx >= 16 * 19456) return;
    int block = idx / 19456;
    int e     = idx % 19456;
    int split = e / 9728;
    int r     = (e % 9728) / 152;
    int k     = e % 152;
    int net = block >> 3, chunk = block & 7;
    int C = chunk * 64 + r;
    int u = C >> 2, g = C & 3;
    int j = g * 128 + u;
    const float* Wih = net ? dWih : eWih;
    const float* Whh = net ? dWhh : eWhh;
    const float* bih = net ? dbih : ebih;
    const float* bhh = net ? dbhh : ebhh;
    float w = 0.f;
    if (k < 128)       w = Whh[j * 128 + k];
    else if (k < 133)  w = Wih[j * 5 + (k - 128)];
    else if (k == 133) w = bih[j] + bhh[j];      // bias lane (A has 1.0 at k=133)
    __half hi = __float2half_rn(w);
    __half v  = split ? __float2half_rn(w - __half2float(hi)) : hi;
    g_wpack[(size_t)block * 19456 + e] = v;
}

__device__ __forceinline__ uint32_t smem_u32(const void* p) {
    uint32_t a;
    asm("{ .reg .u64 t; cvta.to.shared.u64 t, %1; cvt.u32.u64 %0, t; }" : "=r"(a) : "l"(p));
    return a;
}
__device__ __forceinline__ float tanh_fast(float v) {
    float y;
    asm("tanh.approx.f32 %0, %1;" : "=f"(y) : "f"(v));
    return y;
}
__device__ __forceinline__ float sigf(float v) {       // 1 MUFU + 2 FMA
    return fmaf(0.5f, tanh_fast(0.5f * v), 0.5f);
}
__device__ __forceinline__ unsigned short hfu(float v) {
    return __half_as_ushort(__float2half_rn(v));
}
__device__ __forceinline__ float uhf(unsigned short u) {
    return __half2float(__ushort_as_half(u));
}

#define LDSX4(r, addr) \
    asm volatile("ldmatrix.sync.aligned.m8n8.x4.shared.b16 {%0,%1,%2,%3}, [%4];" \
        : "=r"((r)[0]), "=r"((r)[1]), "=r"((r)[2]), "=r"((r)[3]) : "r"(addr) : "memory")

#define MMA16816(d, a, b0, b1) \
    asm volatile("mma.sync.aligned.m16n8k16.row.col.f32.f16.f16.f32 " \
        "{%0,%1,%2,%3},{%4,%5,%6,%7},{%8,%9},{%0,%1,%2,%3};" \
        : "+f"((d)[0]), "+f"((d)[1]), "+f"((d)[2]), "+f"((d)[3]) \
        : "r"((a)[0]), "r"((a)[1]), "r"((a)[2]), "r"((a)[3]), "r"(b0), "r"(b1))

__device__ __forceinline__ void cp_block(int lin, uint32_t dst, int tid) {
    int gblock = ((lin >= 400) ? 8 : 0) + (lin & 7);
    const char* src = (const char*)g_wpack + (size_t)gblock * WBLK;
    #pragma unroll
    for (int i = 0; i < 10; i++) {   // 2432 x 16B over 256 threads
        int idx = tid + i * BDIM;
        if (idx < WBLK / 16) {
            asm volatile("cp.async.ca.shared.global [%0], [%1], 16;"
                         :: "r"(dst + idx * 16), "l"(src + idx * 16) : "memory");
        }
    }
    asm volatile("cp.async.commit_group;" ::: "memory");
}

__global__ void __launch_bounds__(BDIM, 2)
lstm_mma(const float* __restrict__ x,
         const float* __restrict__ linW,
         const float* __restrict__ linb,
         float* __restrict__ out)
{
    extern __shared__ char smem[];
    const uint32_t sb = smem_u32(smem);
    const int tid  = threadIdx.x;
    const int lane = tid & 31;
    const int w    = tid >> 5;       // 0..7
    const int wm   = w & 1;          // M-group: rows wm*32..+31 (2 a-tiles)
    const int wn   = w >> 1;         // N-group: cols wn*16..+15 of 64-col block
    const int base_row = blockIdx.x * ROWS;

    // zero A region (h=0, x pad lanes=0); B gets fully overwritten by cp.async
    {
        uint4 z = make_uint4(0, 0, 0, 0);
        uint4* p = (uint4*)smem;
        for (int i = tid; i < ABUF / 16; i += BDIM) p[i] = z;
    }
    __syncthreads();
    if (tid < ROWS) {   // bias lane k=133 = 1.0 fp16; persists all 62 steps
        *(unsigned short*)(smem + tid * ROWB + 266) = 0x3C00;
    }

    // cell state: 4 cells per iter x 8 iters (dynamic iter -> local memory)
    float c_loc[32];
    #pragma unroll
    for (int i = 0; i < 32; i++) c_loc[i] = 0.f;

    // kt-invariant B-fragment row offset (n16 per warp -> 1 LDSX4 per split)
    const uint32_t brow = (uint32_t)(wn * 16 + ((lane >> 4) << 3) + (lane & 7)) * ROWB
                        + (uint32_t)((lane & 8) << 1);

    cp_block(0, sb + SM_B, tid);
    __syncthreads();

    #pragma unroll 1
    for (int t = 0; t < 62; t++) {
        // stage x(t) into k=128..132 (single A buffer; t=49's write persists
        // as decoder static ctx, velocity overwritten by decoder feedback)
        if (t < 50 && tid < ROWS) {
            const float* xp = x + (size_t)(base_row + tid) * 250 + (size_t)t * 5;
            char* bh = smem + tid * ROWB + 256;   // k=128
            #pragma unroll
            for (int i = 0; i < 5; i++)
                *(unsigned short*)(bh + i * 2) = hfu(xp[i]);
        }
        __syncthreads();   // x staged + prior-step epilogue h writes visible

        // load this warp's full-K A fragments ONCE per step (2 tiles, 72 regs)
        uint32_t ah[9][2][4];
        {
            #pragma unroll
            for (int mt = 0; mt < 2; mt++) {
                const uint32_t ra0 = sb
                    + (uint32_t)(wm * 32 + mt * 16 + (lane & 15)) * ROWB
                    + (uint32_t)(((lane >> 4) << 3) << 1);
                #pragma unroll
                for (int kt = 0; kt < 9; kt++)
                    LDSX4(ah[kt][mt], ra0 + (uint32_t)(kt * 32));
            }
        }
        __syncthreads();   // all frags loaded before epilogue overwrites h

        #pragma unroll 1
        for (int iter = 0; iter < 8; iter++) {
            const int lin = t * 8 + iter;
            asm volatile("cp.async.wait_group 0;" ::: "memory");
            __syncthreads();
            {
                int nl = lin + 1; if (nl > NBLOCKS - 1) nl = NBLOCKS - 1;
                cp_block(nl, sb + SM_B + (uint32_t)(nl & 1) * WBLK, tid);
            }

            const uint32_t wb = sb + SM_B + (uint32_t)(lin & 1) * WBLK + brow;

            float acc[2][2][4];   // [mt][nt(n8)][4]
            #pragma unroll
            for (int mt = 0; mt < 2; mt++)
                #pragma unroll
                for (int nt = 0; nt < 2; nt++)
                    #pragma unroll
                    for (int q = 0; q < 4; q++) acc[mt][nt][q] = 0.f;

            #pragma unroll
            for (int kt = 0; kt < 9; kt++) {
                uint32_t bh_[4], bl_[4];
                const uint32_t ko = (uint32_t)(kt * 32);
                LDSX4(bh_, wb + ko);
                LDSX4(bl_, wb + WSPLIT + ko);
                // sweep 1: Ah . Wh  (4 independent MMAs)
                #pragma unroll
                for (int mt = 0; mt < 2; mt++)
                    #pragma unroll
                    for (int nt = 0; nt < 2; nt++)
                        MMA16816(acc[mt][nt], ah[kt][mt], bh_[nt * 2], bh_[nt * 2 + 1]);
                // sweep 2: Ah . Wl
                #pragma unroll
                for (int mt = 0; mt < 2; mt++)
                    #pragma unroll
                    for (int nt = 0; nt < 2; nt++)
                        MMA16816(acc[mt][nt], ah[kt][mt], bl_[nt * 2], bl_[nt * 2 + 1]);
            }

            // epilogue: warp owns rows [wm*32..+31], units [iter*16+wn*4..+3]
            const int cb_u = iter * 16 + wn * 4;
            const bool even = !(lane & 1);
            #pragma unroll
            for (int mt = 0; mt < 2; mt++) {
                #pragma unroll
                for (int nt = 0; nt < 2; nt++) {
                    float c0 = acc[mt][nt][0], c1 = acc[mt][nt][1];
                    float c2 = acc[mt][nt][2], c3 = acc[mt][nt][3];
                    float x0 = __shfl_xor_sync(0xffffffffu, c0, 1);
                    float x1 = __shfl_xor_sync(0xffffffffu, c1, 1);
                    float x2 = __shfl_xor_sync(0xffffffffu, c2, 1);
                    float x3 = __shfl_xor_sync(0xffffffffu, c3, 1);
                    float iv = even ? c0 : x2;
                    float fv = even ? c1 : x3;
                    float gv = even ? x0 : c2;
                    float ov = even ? x1 : c3;
                    int row = wm * 32 + mt * 16 + (lane >> 2) + (even ? 0 : 8);
                    int ug  = cb_u + nt * 2 + ((lane & 3) >> 1);
                    int ci  = iter * 4 + mt * 2 + nt;
                    float ivs = sigf(iv), fvs = sigf(fv);
                    float gvt = tanh_fast(gv), ovs = sigf(ov);
                    float cn = fmaf(fvs, c_loc[ci], ivs * gvt);
                    c_loc[ci] = cn;
                    float hv = ovs * tanh_fast(cn);
                    *(unsigned short*)(smem + row * ROWB + ug * 2) = hfu(hv);
                }
            }
        }

        if (t >= 50) {   // pred = h_new @ linW^T + linb; feed back velocity
            __syncthreads();   // all epilogue writes of this step visible
            if (tid < 2 * ROWS) {
                int r = tid & (ROWS - 1), jj = tid >> 6;
                const char* bh = smem + r * ROWB;
                float accp = __ldg(linb + jj);
                const float* lw = linW + jj * 128;
                #pragma unroll 16
                for (int u = 0; u < 128; u++)
                    accp = fmaf(uhf(*(const unsigned short*)(bh + u * 2)),
                                __ldg(lw + u), accp);
                out[((size_t)(base_row + r) * 12 + (t - 50)) * 2 + jj] = accp;
                *(unsigned short*)(smem + r * ROWB + (128 + jj) * 2) = hfu(accp);
            }
        }
    }
}

extern "C" void kernel_launch(void* const* d_in, const int* in_sizes, int n_in,
                              void* d_out, int out_size)
{
    const float* x    = (const float*)d_in[0];
    const float* eWih = (const float*)d_in[1];
    const float* eWhh = (const float*)d_in[2];
    const float* ebih = (const float*)d_in[3];
    const float* ebhh = (const float*)d_in[4];
    const float* dWih = (const float*)d_in[5];
    const float* dWhh = (const float*)d_in[6];
    const float* dbih = (const float*)d_in[7];
    const float* dbhh = (const float*)d_in[8];
    const float* lW   = (const float*)d_in[9];
    const float* lb   = (const float*)d_in[10];
    float* out = (float*)d_out;

    cudaFuncSetAttribute(lstm_mma, cudaFuncAttributeMaxDynamicSharedMemorySize, SMEM_TOTAL);

    prep_kernel<<<(16 * 19456 + 255) / 256, 256>>>(eWih, eWhh, ebih, ebhh,
                                                   dWih, dWhh, dbih, dbhh);
    lstm_mma<<<256, BDIM, SMEM_TOTAL>>>(x, lW, lb, out);
}

// round 17
// speedup vs baseline: 1.4800x; 1.4800x over previous
#include <cuda_runtime.h>
#include <cuda_fp16.h>
#include <stdint.h>

// ContextAwareTracker: LSTM enc(50)+dec(12), B=16384, H=128, I=5.
// Round 17: R15 base (R16 reverted: 2 CTA/SM gave same 16 warps/SM but 2x W
// traffic -> -10%). Work cut: SINGLE fp16 W term (drop Wl sweep):
//  - prep quantizes W with error-diffusion along k (per-column sum of
//    rounding errors ~0 -> kills DC systematic preact error)
//  - MMAs/iter 72 -> 36; B LDSM and W cp.async traffic halve; smem 76KB
//  - A-side unchanged (single fp16, fresh noise/step, forget-gate damped)
// Risk axis: rel_err predicted 3-6e-4 vs 1e-3 gate; fallback = reinstate Wl.
// NOTE: tcgen05 unavailable (harness PTX target sm_103 base) - mma.sync only.

#define BDIM 512
#define ROWB 304          // conflict-free ldmatrix stride; K pad 152
#define ABUF 38912        // 128 * 304, single fp16 A buffer
#define SM_B ABUF
#define WBLK 19456        // 64 cols x 304B (single split)
#define SMEM_TOTAL (ABUF + 2 * WBLK)   // 77824
#define NBLOCKS 496       // 62 steps * 8 blocks

__device__ __half g_wpack[16 * 9728];  // [net 2][chunk64 8][n 64][k 152]

// gate col interleave: C = 4*unit + gate (0=i,1=f,2=g,3=o)
// One thread per weight column: error-diffusion quantization along k.
__global__ void prep_kernel(const float* __restrict__ eWih, const float* __restrict__ eWhh,
                            const float* __restrict__ ebih, const float* __restrict__ ebhh,
                            const float* __restrict__ dWih, const float* __restrict__ dWhh,
                            const float* __restrict__ dbih, const float* __restrict__ dbhh)
{
    int col = blockIdx.x * blockDim.x + threadIdx.x;
    if (col >= 1024) return;            // 2 nets x 512 gate-cols
    int net = col >> 9;
    int C   = col & 511;
    int chunk = C >> 6, r = C & 63;
    int u = C >> 2, g = C & 3;
    int j = g * 128 + u;
    const float* Wih = net ? dWih : eWih;
    const float* Whh = net ? dWhh : eWhh;
    const float* bih = net ? dbih : ebih;
    const float* bhh = net ? dbhh : ebhh;
    __half* dst = g_wpack + (size_t)(net * 8 + chunk) * 9728 + (size_t)r * 152;
    float carry = 0.f;
    for (int k = 0; k < 152; k++) {
        float w;
        if (k < 128)       w = Whh[j * 128 + k];
        else if (k < 133)  w = Wih[j * 5 + (k - 128)];
        else if (k == 133) w = bih[j] + bhh[j];   // bias lane (A has 1.0)
        else               w = 0.f;
        __half q;
        if (k == 133 || k >= 134) {               // bias/pad: plain rn
            q = __float2half_rn(w);
        } else {                                  // error diffusion
            float v = w + carry;
            q = __float2half_rn(v);
            carry = v - __half2float(q);
        }
        dst[k] = q;
    }
}

__device__ __forceinline__ uint32_t smem_u32(const void* p) {
    uint32_t a;
    asm("{ .reg .u64 t; cvta.to.shared.u64 t, %1; cvt.u32.u64 %0, t; }" : "=r"(a) : "l"(p));
    return a;
}
__device__ __forceinline__ float tanh_fast(float v) {
    float y;
    asm("tanh.approx.f32 %0, %1;" : "=f"(y) : "f"(v));
    return y;
}
__device__ __forceinline__ float sigf(float v) {       // 1 MUFU + 2 FMA
    return fmaf(0.5f, tanh_fast(0.5f * v), 0.5f);
}
__device__ __forceinline__ unsigned short hfu(float v) {
    return __half_as_ushort(__float2half_rn(v));
}
__device__ __forceinline__ float uhf(unsigned short u) {
    return __half2float(__ushort_as_half(u));
}

#define LDSX4(r, addr) \
    asm volatile("ldmatrix.sync.aligned.m8n8.x4.shared.b16 {%0,%1,%2,%3}, [%4];" \
        : "=r"((r)[0]), "=r"((r)[1]), "=r"((r)[2]), "=r"((r)[3]) : "r"(addr) : "memory")

#define MMA16816(d, a, b0, b1) \
    asm volatile("mma.sync.aligned.m16n8k16.row.col.f32.f16.f16.f32 " \
        "{%0,%1,%2,%3},{%4,%5,%6,%7},{%8,%9},{%0,%1,%2,%3};" \
        : "+f"((d)[0]), "+f"((d)[1]), "+f"((d)[2]), "+f"((d)[3]) \
        : "r"((a)[0]), "r"((a)[1]), "r"((a)[2]), "r"((a)[3]), "r"(b0), "r"(b1))

__device__ __forceinline__ void cp_block(int lin, uint32_t dst, int tid) {
    int gblock = ((lin >= 400) ? 8 : 0) + (lin & 7);
    const char* src = (const char*)g_wpack + (size_t)gblock * WBLK;
    #pragma unroll
    for (int i = 0; i < 3; i++) {   // 1216 x 16B over 512 threads
        int idx = tid + i * BDIM;
        if (idx < WBLK / 16) {
            asm volatile("cp.async.ca.shared.global [%0], [%1], 16;"
                         :: "r"(dst + idx * 16), "l"(src + idx * 16) : "memory");
        }
    }
    asm volatile("cp.async.commit_group;" ::: "memory");
}

__global__ void __launch_bounds__(BDIM, 1)
lstm_mma(const float* __restrict__ x,
         const float* __restrict__ linW,
         const float* __restrict__ linb,
         float* __restrict__ out)
{
    extern __shared__ char smem[];
    const uint32_t sb = smem_u32(smem);
    const int tid  = threadIdx.x;
    const int lane = tid & 31;
    const int w    = tid >> 5;       // 0..15
    const int wm   = w & 3;          // M-group: rows wm*32..+31 (2 a-tiles)
    const int wn   = w >> 2;         // N-group: cols wn*16..+15 of 64-col block
    const int base_row = blockIdx.x * 128;

    // zero A region (h=0, x pad lanes=0); B gets fully overwritten by cp.async
    {
        uint4 z = make_uint4(0, 0, 0, 0);
        uint4* p = (uint4*)smem;
        for (int i = tid; i < ABUF / 16; i += BDIM) p[i] = z;
    }
    __syncthreads();
    if (tid < 128) {    // bias lane k=133 = 1.0 fp16; persists all 62 steps
        *(unsigned short*)(smem + tid * ROWB + 266) = 0x3C00;
    }

    // cell state: 4 cells per iter x 8 iters (dynamic iter -> local memory)
    float c_loc[32];
    #pragma unroll
    for (int i = 0; i < 32; i++) c_loc[i] = 0.f;

    // kt-invariant B-fragment row offset (n16 per warp -> 1 LDSX4 per kt)
    const uint32_t brow = (uint32_t)(wn * 16 + ((lane >> 4) << 3) + (lane & 7)) * ROWB
                        + (uint32_t)((lane & 8) << 1);

    cp_block(0, sb + SM_B, tid);
    __syncthreads();

    #pragma unroll 1
    for (int t = 0; t < 62; t++) {
        // stage x(t) into k=128..132 (single A buffer; t=49's write persists
        // as decoder static ctx, velocity overwritten by decoder feedback)
        if (t < 50 && tid < 128) {
            const float* xp = x + (size_t)(base_row + tid) * 250 + (size_t)t * 5;
            char* bh = smem + tid * ROWB + 256;   // k=128
            #pragma unroll
            for (int i = 0; i < 5; i++)
                *(unsigned short*)(bh + i * 2) = hfu(xp[i]);
        }
        __syncthreads();   // x staged + prior-step epilogue h writes visible

        // load this warp's full-K A fragments ONCE per step (2 tiles, 72 regs)
        uint32_t ah[9][2][4];
        {
            #pragma unroll
            for (int mt = 0; mt < 2; mt++) {
                const uint32_t ra0 = sb
                    + (uint32_t)(wm * 32 + mt * 16 + (lane & 15)) * ROWB
                    + (uint32_t)(((lane >> 4) << 3) << 1);
                #pragma unroll
                for (int kt = 0; kt < 9; kt++)
                    LDSX4(ah[kt][mt], ra0 + (uint32_t)(kt * 32));
            }
        }
        __syncthreads();   // all frags loaded before epilogue overwrites h

        #pragma unroll 1
        for (int iter = 0; iter < 8; iter++) {
            const int lin = t * 8 + iter;
            asm volatile("cp.async.wait_group 0;" ::: "memory");
            __syncthreads();
            {
                int nl = lin + 1; if (nl > NBLOCKS - 1) nl = NBLOCKS - 1;
                cp_block(nl, sb + SM_B + (uint32_t)(nl & 1) * WBLK, tid);
            }

            const uint32_t wb = sb + SM_B + (uint32_t)(lin & 1) * WBLK + brow;

            float acc[2][2][4];   // [mt][nt(n8)][4]
            #pragma unroll
            for (int mt = 0; mt < 2; mt++)
                #pragma unroll
                for (int nt = 0; nt < 2; nt++)
                    #pragma unroll
                    for (int q = 0; q < 4; q++) acc[mt][nt][q] = 0.f;

            #pragma unroll
            for (int kt = 0; kt < 9; kt++) {
                uint32_t bh_[4];
                LDSX4(bh_, wb + (uint32_t)(kt * 32));
                #pragma unroll
                for (int mt = 0; mt < 2; mt++)
                    #pragma unroll
                    for (int nt = 0; nt < 2; nt++)
                        MMA16816(acc[mt][nt], ah[kt][mt], bh_[nt * 2], bh_[nt * 2 + 1]);
            }

            // epilogue: warp owns rows [wm*32..+31], units [iter*16+wn*4..+3]
            const int cb_u = iter * 16 + wn * 4;
            const bool even = !(lane & 1);
            #pragma unroll
            for (int mt = 0; mt < 2; mt++) {
                #pragma unroll
                for (int nt = 0; nt < 2; nt++) {
                    float c0 = acc[mt][nt][0], c1 = acc[mt][nt][1];
                    float c2 = acc[mt][nt][2], c3 = acc[mt][nt][3];
                    float x0 = __shfl_xor_sync(0xffffffffu, c0, 1);
                    float x1 = __shfl_xor_sync(0xffffffffu, c1, 1);
                    float x2 = __shfl_xor_sync(0xffffffffu, c2, 1);
                    float x3 = __shfl_xor_sync(0xffffffffu, c3, 1);
                    float iv = even ? c0 : x2;
                    float fv = even ? c1 : x3;
                    float gv = even ? x0 : c2;
                    float ov = even ? x1 : c3;
                    int row = wm * 32 + mt * 16 + (lane >> 2) + (even ? 0 : 8);
                    int ug  = cb_u + nt * 2 + ((lane & 3) >> 1);
                    int ci  = iter * 4 + mt * 2 + nt;
                    float ivs = sigf(iv), fvs = sigf(fv);
                    float gvt = tanh_fast(gv), ovs = sigf(ov);
                    float cn = fmaf(fvs, c_loc[ci], ivs * gvt);
                    c_loc[ci] = cn;
                    float hv = ovs * tanh_fast(cn);
                    *(unsigned short*)(smem + row * ROWB + ug * 2) = hfu(hv);
                }
            }
        }

        if (t >= 50) {   // pred = h_new @ linW^T + linb; feed back velocity
            __syncthreads();   // all epilogue writes of this step visible
            if (tid < 256) {
                int r = tid & 127, jj = tid >> 7;
                const char* bh = smem + r * ROWB;
                float accp = __ldg(linb + jj);
                const float* lw = linW + jj * 128;
                #pragma unroll 16
                for (int u = 0; u < 128; u++)
                    accp = fmaf(uhf(*(const unsigned short*)(bh + u * 2)),
                                __ldg(lw + u), accp);
                out[((size_t)(base_row + r) * 12 + (t - 50)) * 2 + jj] = accp;
                *(unsigned short*)(smem + r * ROWB + (128 + jj) * 2) = hfu(accp);
            }
        }
    }
}

extern "C" void kernel_launch(void* const* d_in, const int* in_sizes, int n_in,
                              void* d_out, int out_size)
{
    const float* x    = (const float*)d_in[0];
    const float* eWih = (const float*)d_in[1];
    const float* eWhh = (const float*)d_in[2];
    const float* ebih = (const float*)d_in[3];
    const float* ebhh = (const float*)d_in[4];
    const float* dWih = (const float*)d_in[5];
    const float* dWhh = (const float*)d_in[6];
    const float* dbih = (const float*)d_in[7];
    const float* dbhh = (const float*)d_in[8];
    const float* lW   = (const float*)d_in[9];
    const float* lb   = (const float*)d_in[10];
    float* out = (float*)d_out;

    cudaFuncSetAttribute(lstm_mma, cudaFuncAttributeMaxDynamicSharedMemorySize, SMEM_TOTAL);

    prep_kernel<<<4, 256>>>(eWih, eWhh, ebih, ebhh, dWih, dWhh, dbih, dbhh);
    lstm_mma<<<128, BDIM, SMEM_TOTAL>>>(x, lW, lb, out);
}